// round 17
// baseline (speedup 1.0000x reference)
#include <cuda_runtime.h>
#include <cuda_fp16.h>
#include <cstdint>
#include <math.h>

// Problem constants
#define SEQ   4096
#define NH    16
#define HD    64
#define DIM   1024
#define NQKV  3072
#define WIN_HALF 128
#define NGLOB 64

// ---------------------------------------------------------------------------
// Device-global scratch (allocation-free rule)
// Q/K stored as split fp16 hi/lo; V as plain fp16 (bit-identical to the
// previous fp32-then-split path since the split happens on the same fp32 acc).
// ---------------------------------------------------------------------------
__device__ __half g_Qh[NH * SEQ * HD];
__device__ __half g_Ql[NH * SEQ * HD];
__device__ __half g_Kh[NH * SEQ * HD];
__device__ __half g_Kl[NH * SEQ * HD];
__device__ __half g_Vh[NH * SEQ * HD];
__device__ __half g_x[SEQ * DIM];                  // x fp16 [S][K]
__device__ __half g_wqT[NQKV * DIM];               // w_qkv^T fp16 [N][K]
__device__ __half g_woT[DIM * DIM];                // w_out^T fp16 [N][K]
__device__ __half g_a[SEQ * DIM];                  // attn out fp16 [S][H*D]

// ---------------------------------------------------------------------------
// Baseline-PTX helpers
// ---------------------------------------------------------------------------
__device__ __forceinline__ uint32_t smem_to_u32(const void* smem_ptr) {
    uint32_t addr;
    asm("{ .reg .u64 tmp; cvta.to.shared.u64 tmp, %1; cvt.u32.u64 %0, tmp; }"
        : "=r"(addr) : "l"(smem_ptr));
    return addr;
}

__device__ __forceinline__ void cp_async16(uint32_t dst, const void* src) {
    asm volatile("cp.async.cg.shared.global [%0], [%1], 16;"
                 :: "r"(dst), "l"(src));
}
#define CP_ASYNC_COMMIT() asm volatile("cp.async.commit_group;" ::: "memory")
#define CP_ASYNC_WAIT_2() asm volatile("cp.async.wait_group 2;" ::: "memory")
#define CP_ASYNC_WAIT_0() asm volatile("cp.async.wait_group 0;" ::: "memory")

__device__ __forceinline__ void ldsm_x4(uint32_t& r0, uint32_t& r1,
                                        uint32_t& r2, uint32_t& r3, uint32_t addr) {
    asm volatile("ldmatrix.sync.aligned.m8n8.x4.shared.b16 {%0,%1,%2,%3}, [%4];"
                 : "=r"(r0), "=r"(r1), "=r"(r2), "=r"(r3) : "r"(addr));
}

__device__ __forceinline__ void ldsm_x4_t(uint32_t& r0, uint32_t& r1,
                                          uint32_t& r2, uint32_t& r3, uint32_t addr) {
    asm volatile("ldmatrix.sync.aligned.m8n8.x4.trans.shared.b16 {%0,%1,%2,%3}, [%4];"
                 : "=r"(r0), "=r"(r1), "=r"(r2), "=r"(r3) : "r"(addr));
}

__device__ __forceinline__ void mma_f16(float* c, const uint32_t* a, const uint32_t* b) {
    asm volatile(
        "mma.sync.aligned.m16n8k16.row.col.f32.f16.f16.f32 "
        "{%0,%1,%2,%3}, {%4,%5,%6,%7}, {%8,%9}, {%0,%1,%2,%3};"
        : "+f"(c[0]), "+f"(c[1]), "+f"(c[2]), "+f"(c[3])
        : "r"(a[0]), "r"(a[1]), "r"(a[2]), "r"(a[3]), "r"(b[0]), "r"(b[1]));
}

__device__ __forceinline__ void split_h(float v, __half& h, __half& l) {
    h = __float2half_rn(v);
    l = __float2half_rn(v - __half2float(h));
}

__device__ __forceinline__ uint32_t pack_h2(__half a, __half b) {
    __half2 t = __halves2half2(a, b);
    return *reinterpret_cast<uint32_t*>(&t);
}

// ---------------------------------------------------------------------------
// Pre-pass 1: round x -> g_x (fp16)
// ---------------------------------------------------------------------------
__global__ void conv_x_kernel(const float* __restrict__ x) {
    const int i = (blockIdx.x * blockDim.x + threadIdx.x) * 4;
    float4 v = *reinterpret_cast<const float4*>(x + i);
    g_x[i + 0] = __float2half_rn(v.x);
    g_x[i + 1] = __float2half_rn(v.y);
    g_x[i + 2] = __float2half_rn(v.z);
    g_x[i + 3] = __float2half_rn(v.w);
}

// ---------------------------------------------------------------------------
// Pre-pass 2 (merged): transpose both weights [K][N] -> [N][K] fp16.
// blockIdx.x < 96 -> w_qkv col-tiles; else -> w_out col-tiles.
// ---------------------------------------------------------------------------
__global__ void tconv_kernel(const float* __restrict__ Wq,
                             const float* __restrict__ Wo) {
    __shared__ float t[32][33];
    const bool isq = blockIdx.x < (NQKV / 32);
    const float* W = isq ? Wq : Wo;
    __half* dst = isq ? g_wqT : g_woT;
    const int N = isq ? NQKV : DIM;
    const int n0 = (isq ? blockIdx.x : blockIdx.x - NQKV / 32) * 32;
    const int k0 = blockIdx.y * 32;
    const int tx = threadIdx.x, ty = threadIdx.y;
#pragma unroll
    for (int i = 0; i < 32; i += 8)
        t[ty + i][tx] = W[(size_t)(k0 + ty + i) * N + n0 + tx];
    __syncthreads();
#pragma unroll
    for (int i = 0; i < 32; i += 8)
        dst[(size_t)(n0 + ty + i) * DIM + k0 + tx] = __float2half_rn(t[tx][ty + i]);
}

// ---------------------------------------------------------------------------
// HMMA GEMM: single-term fp16, 128x128 tile, BK=32, 128 threads, 3-stage
// cp.async. Now __launch_bounds__(128, 3) -> 3 CTAs/SM (180KB smem, <=170 regs).
// mode 0: scatter split-fp16 Q/K (hi/lo) + fp16 V; mode 1: write fp32 Cout.
// ---------------------------------------------------------------------------
#define AP_BYTES   80
#define T_TILE     10240
#define STAGE_B    20480
#define N_STAGE    3
#define GEMM_SMEM  (N_STAGE * STAGE_B)

__global__ void __launch_bounds__(128, 3) gemm_mma_kernel(float* __restrict__ Cout, int mode)
{
    extern __shared__ char smem_raw[];
    const uint32_t sb = smem_to_u32(smem_raw);

    const int tid  = threadIdx.x;
    const int wid  = tid >> 5;
    const int lane = tid & 31;
    const int wm   = wid & 1;
    const int wn   = wid >> 1;
    const int m0   = blockIdx.y * 128;
    const int n0   = blockIdx.x * 128;

    const __half *A, *B;
    if (mode == 0) { A = g_x; B = g_wqT; }
    else           { A = g_a; B = g_woT; }

    auto load_stage = [&](int stage, int kt) {
        const int k0 = kt * 32;
        const uint32_t sbase = sb + stage * STAGE_B;
#pragma unroll
        for (int e = 0; e < 8; e++) {
            const int cid  = e * 128 + tid;
            const int tile = cid >> 9;
            const int idx  = cid & 511;
            const int r    = idx >> 2;
            const int ch   = idx & 3;
            const __half* src = (tile == 0)
                ? A + (size_t)(m0 + r) * DIM + k0 + ch * 8
                : B + (size_t)(n0 + r) * DIM + k0 + ch * 8;
            cp_async16(sbase + tile * T_TILE + r * AP_BYTES + ch * 16, src);
        }
    };

    const uint32_t a_off = (uint32_t)((wm * 64 + (lane & 15)) * AP_BYTES + (lane >> 4) * 16);
    const uint32_t b_off = (uint32_t)((wn * 64 + (lane & 15)) * AP_BYTES + (lane >> 4) * 16) + (uint32_t)T_TILE;

    float acc[4][8][4];
#pragma unroll
    for (int i = 0; i < 4; i++)
#pragma unroll
        for (int j = 0; j < 8; j++)
#pragma unroll
            for (int e = 0; e < 4; e++) acc[i][j][e] = 0.0f;

    load_stage(0, 0); CP_ASYNC_COMMIT();
    load_stage(1, 1); CP_ASYNC_COMMIT();
    load_stage(2, 2); CP_ASYNC_COMMIT();

    int stg = 0;
    for (int kt = 0; kt < 32; kt++) {
        CP_ASYNC_WAIT_2();
        __syncthreads();
        const uint32_t sbase = sb + (uint32_t)stg * STAGE_B;

#pragma unroll
        for (int ks = 0; ks < 2; ks++) {
            uint32_t ah[4][4], bh[8][2];
#pragma unroll
            for (int i = 0; i < 4; i++) {
                const uint32_t ad = sbase + a_off + i * (16 * AP_BYTES) + ks * 32;
                ldsm_x4(ah[i][0], ah[i][1], ah[i][2], ah[i][3], ad);
            }
#pragma unroll
            for (int p = 0; p < 4; p++) {
                const uint32_t bd = sbase + b_off + p * (16 * AP_BYTES) + ks * 32;
                uint32_t t0, t1, t2, t3;
                ldsm_x4(t0, t1, t2, t3, bd);
                bh[2*p][0] = t0; bh[2*p][1] = t2; bh[2*p+1][0] = t1; bh[2*p+1][1] = t3;
            }
#pragma unroll
            for (int i = 0; i < 4; i++)
#pragma unroll
                for (int j = 0; j < 8; j++) mma_f16(acc[i][j], ah[i], bh[j]);
        }

        __syncthreads();
        if (kt + 3 < 32) load_stage(stg, kt + 3);
        CP_ASYNC_COMMIT();
        stg = (stg == N_STAGE - 1) ? 0 : stg + 1;
    }

    const int mbase = m0 + wm * 64 + (lane >> 2);
    const int nbase = n0 + wn * 64 + (lane & 3) * 2;
#pragma unroll
    for (int i = 0; i < 4; i++) {
        const int mlo = mbase + i * 16;
#pragma unroll
        for (int j = 0; j < 8; j++) {
            const int n = nbase + j * 8;
            if (mode == 0) {
                const int t = n >> 10, rem = n & 1023, h = rem >> 6, d = rem & 63;
                const size_t o0 = (size_t)h * SEQ * HD + (size_t)mlo * HD + d;
                const size_t o1 = o0 + 8 * HD;
                if (t == 2) {
                    *reinterpret_cast<__half2*>(g_Vh + o0) =
                        __halves2half2(__float2half_rn(acc[i][j][0]), __float2half_rn(acc[i][j][1]));
                    *reinterpret_cast<__half2*>(g_Vh + o1) =
                        __halves2half2(__float2half_rn(acc[i][j][2]), __float2half_rn(acc[i][j][3]));
                } else {
                    __half* dh = (t == 0) ? g_Qh : g_Kh;
                    __half* dl = (t == 0) ? g_Ql : g_Kl;
                    __half h0, l0, h1, l1;
                    split_h(acc[i][j][0], h0, l0); split_h(acc[i][j][1], h1, l1);
                    *reinterpret_cast<__half2*>(dh + o0) = __halves2half2(h0, h1);
                    *reinterpret_cast<__half2*>(dl + o0) = __halves2half2(l0, l1);
                    split_h(acc[i][j][2], h0, l0); split_h(acc[i][j][3], h1, l1);
                    *reinterpret_cast<__half2*>(dh + o1) = __halves2half2(h0, h1);
                    *reinterpret_cast<__half2*>(dl + o1) = __halves2half2(l0, l1);
                }
            } else {
                float2 v0; v0.x = acc[i][j][0]; v0.y = acc[i][j][1];
                float2 v1; v1.x = acc[i][j][2]; v1.y = acc[i][j][3];
                *reinterpret_cast<float2*>(Cout + (size_t)mlo * DIM + n)       = v0;
                *reinterpret_cast<float2*>(Cout + (size_t)(mlo + 8) * DIM + n) = v1;
            }
        }
    }
}

// ---------------------------------------------------------------------------
// Attention on HMMA: flash-style online softmax over <=4 key tiles of 64.
// Q/K/V arrive pre-split fp16 -> tile loads are pure cp.async (no conversion).
// QK^T 3-term split; P*V 2-term. 128 threads, 4 warps x 16 query rows.
// ---------------------------------------------------------------------------
#define APH       72                     // smem pitch in halves (144 B)
#define QSH_B     0
#define QSL_B     (64 * APH * 2)
#define KSH_B     (2 * 64 * APH * 2)
#define KSL_B     (3 * 64 * APH * 2)
#define VSH_B     (4 * 64 * APH * 2)
#define ATTN_SMEM (5 * 64 * APH * 2)     // 46080 bytes

__global__ void __launch_bounds__(128) attn_kernel()
{
    extern __shared__ __half smh[];
    const uint32_t sb = smem_to_u32(smh);

    const int h  = blockIdx.y;
    const int qt = blockIdx.x;
    const int qbase = qt * 64;

    const int tid  = threadIdx.x;
    const int w    = tid >> 5;
    const int lane = tid & 31;

    const size_t hb = (size_t)h * SEQ * HD;

    // Q tiles (hi/lo): 2 x 512 16B-chunks, 8 per thread, pure cp.async.
#pragma unroll
    for (int e = 0; e < 8; e++) {
        const int idx = tid + e * 128;          // 0..1023
        const int tile = idx >> 9;              // 0: Qh, 1: Ql
        const int k = idx & 511;
        const int r = k >> 3, ch = k & 7;
        const __half* src = (tile ? g_Ql : g_Qh) + hb + (size_t)(qbase + r) * HD + ch * 8;
        cp_async16(sb + (tile ? QSL_B : QSH_B) + r * (APH * 2) + ch * 16, src);
    }
    CP_ASYNC_COMMIT();

    float acc_o[8][4];
#pragma unroll
    for (int j = 0; j < 8; j++)
#pragma unroll
        for (int e = 0; e < 4; e++) acc_o[j][e] = 0.0f;
    float m_r[2] = {-1e30f, -1e30f};
    float l_r[2] = {0.0f, 0.0f};

    int starts[4];
    int ns = 0;
    starts[ns++] = 0;
    if (qbase - 128 > 0) starts[ns++] = qbase - 128;
    if (qbase - 64  > 0) starts[ns++] = qbase - 64;
    if (qbase       > 0) starts[ns++] = qbase;

    const int r0 = qbase + w * 16 + (lane >> 2);   // global query row (low)

    for (int it = 0; it < ns; it++) {
        const int kst = starts[it];
        __syncthreads();   // previous tile's smem consumers done

        // K (hi/lo) + V tiles: 3 x 512 chunks, 12 per thread.
#pragma unroll
        for (int e = 0; e < 12; e++) {
            const int idx = tid + e * 128;      // 0..1535
            const int tile = idx >> 9;          // 0: Kh, 1: Kl, 2: Vh
            const int k = idx & 511;
            const int r = k >> 3, ch = k & 7;
            const __half* srcb = (tile == 0) ? g_Kh : (tile == 1) ? g_Kl : g_Vh;
            const uint32_t dstb = (tile == 0) ? KSH_B : (tile == 1) ? KSL_B : VSH_B;
            cp_async16(sb + dstb + r * (APH * 2) + ch * 16,
                       srcb + hb + (size_t)(kst + r) * HD + ch * 8);
        }
        CP_ASYNC_COMMIT();
        CP_ASYNC_WAIT_0();
        __syncthreads();

        // ---- S = Q K^T  (3-term split) ----
        float s[8][4];
#pragma unroll
        for (int j = 0; j < 8; j++)
#pragma unroll
            for (int e = 0; e < 4; e++) s[j][e] = 0.0f;

        const uint32_t arow = (uint32_t)((w * 16 + (lane & 15)) * (APH * 2) + (lane >> 4) * 16);
        const uint32_t brow = (uint32_t)(((lane & 15)) * (APH * 2) + (lane >> 4) * 16);

#pragma unroll
        for (int kk = 0; kk < 4; kk++) {
            uint32_t aqh[4], aql[4];
            ldsm_x4(aqh[0], aqh[1], aqh[2], aqh[3], sb + QSH_B + arow + kk * 32);
            ldsm_x4(aql[0], aql[1], aql[2], aql[3], sb + QSL_B + arow + kk * 32);
#pragma unroll
            for (int p = 0; p < 4; p++) {
                uint32_t t0, t1, t2, t3;
                uint32_t bh[2], bl[2];
                const uint32_t koff = (uint32_t)(p * 16 * (APH * 2)) + kk * 32;
                ldsm_x4(t0, t1, t2, t3, sb + KSH_B + brow + koff);
                bh[0] = t0; bh[1] = t2;
                uint32_t bh1[2]; bh1[0] = t1; bh1[1] = t3;
                ldsm_x4(t0, t1, t2, t3, sb + KSL_B + brow + koff);
                bl[0] = t0; bl[1] = t2;
                uint32_t bl1[2]; bl1[0] = t1; bl1[1] = t3;
                mma_f16(s[2*p],   aqh, bh);
                mma_f16(s[2*p+1], aqh, bh1);
                mma_f16(s[2*p],   aql, bh);
                mma_f16(s[2*p+1], aql, bh1);
                mma_f16(s[2*p],   aqh, bl);
                mma_f16(s[2*p+1], aqh, bl1);
            }
        }

        // ---- mask + scale + online softmax (fp32 on fragments) ----
        const int colb = kst + (lane & 3) * 2;
        float mx[2] = {-1e30f, -1e30f};
#pragma unroll
        for (int j = 0; j < 8; j++) {
            const int c0 = colb + j * 8;
#pragma unroll
            for (int e = 0; e < 4; e++) {
                const int col = c0 + (e & 1);
                const int row = (e < 2) ? r0 : (r0 + 8);
                const bool valid = (col <= row) && ((col >= row - WIN_HALF) || (col < NGLOB));
                const float v = valid ? s[j][e] * 0.125f : -1e30f;
                s[j][e] = v;
                mx[e >> 1] = fmaxf(mx[e >> 1], v);
            }
        }
#pragma unroll
        for (int off = 1; off < 4; off <<= 1) {
            mx[0] = fmaxf(mx[0], __shfl_xor_sync(0xffffffffu, mx[0], off));
            mx[1] = fmaxf(mx[1], __shfl_xor_sync(0xffffffffu, mx[1], off));
        }
        float alpha[2], psum[2];
#pragma unroll
        for (int e = 0; e < 2; e++) {
            const float mnew = fmaxf(m_r[e], mx[e]);
            alpha[e] = __expf(m_r[e] - mnew);
            m_r[e] = mnew;
            l_r[e] *= alpha[e];
            psum[e] = 0.0f;
        }
#pragma unroll
        for (int j = 0; j < 8; j++) {
            s[j][0] = __expf(s[j][0] - m_r[0]);
            s[j][1] = __expf(s[j][1] - m_r[0]);
            s[j][2] = __expf(s[j][2] - m_r[1]);
            s[j][3] = __expf(s[j][3] - m_r[1]);
            psum[0] += s[j][0] + s[j][1];
            psum[1] += s[j][2] + s[j][3];
            acc_o[j][0] *= alpha[0]; acc_o[j][1] *= alpha[0];
            acc_o[j][2] *= alpha[1]; acc_o[j][3] *= alpha[1];
        }
#pragma unroll
        for (int off = 1; off < 4; off <<= 1) {
            psum[0] += __shfl_xor_sync(0xffffffffu, psum[0], off);
            psum[1] += __shfl_xor_sync(0xffffffffu, psum[1], off);
        }
        l_r[0] += psum[0];
        l_r[1] += psum[1];

        // ---- P fragments: C-layout -> A-layout, fp16 hi/lo split ----
        uint32_t aph[4][4], apl[4][4];
#pragma unroll
        for (int kk = 0; kk < 4; kk++) {
            const int j0 = 2 * kk, j1 = 2 * kk + 1;
            __half h0, h1, l0, l1;
            split_h(s[j0][0], h0, l0); split_h(s[j0][1], h1, l1);
            aph[kk][0] = pack_h2(h0, h1); apl[kk][0] = pack_h2(l0, l1);
            split_h(s[j0][2], h0, l0); split_h(s[j0][3], h1, l1);
            aph[kk][1] = pack_h2(h0, h1); apl[kk][1] = pack_h2(l0, l1);
            split_h(s[j1][0], h0, l0); split_h(s[j1][1], h1, l1);
            aph[kk][2] = pack_h2(h0, h1); apl[kk][2] = pack_h2(l0, l1);
            split_h(s[j1][2], h0, l0); split_h(s[j1][3], h1, l1);
            aph[kk][3] = pack_h2(h0, h1); apl[kk][3] = pack_h2(l0, l1);
        }

        // ---- O += P V  (2-term; V via ldmatrix.trans from [k][d]) ----
#pragma unroll
        for (int kk = 0; kk < 4; kk++) {
            const uint32_t vrow = sb + VSH_B +
                (uint32_t)((kk * 16 + (lane & 15)) * (APH * 2));
#pragma unroll
            for (int p2 = 0; p2 < 4; p2++) {
                uint32_t t0, t1, t2, t3;
                ldsm_x4_t(t0, t1, t2, t3, vrow + p2 * 32 + (lane >> 4) * 16);
                uint32_t bv0[2]; bv0[0] = t0; bv0[1] = t1;
                uint32_t bv1[2]; bv1[0] = t2; bv1[1] = t3;
                mma_f16(acc_o[2*p2],   aph[kk], bv0);
                mma_f16(acc_o[2*p2+1], aph[kk], bv1);
                mma_f16(acc_o[2*p2],   apl[kk], bv0);
                mma_f16(acc_o[2*p2+1], apl[kk], bv1);
            }
        }
    }

    // ---- epilogue: normalize, store fp16 to g_a [S][H*D] ----
    const float inv0 = 1.0f / l_r[0];
    const float inv1 = 1.0f / l_r[1];
    const int colb = h * HD + (lane & 3) * 2;
#pragma unroll
    for (int j2 = 0; j2 < 8; j2++) {
        const int col = colb + j2 * 8;
        __half2 v0 = __halves2half2(__float2half_rn(acc_o[j2][0] * inv0),
                                    __float2half_rn(acc_o[j2][1] * inv0));
        __half2 v1 = __halves2half2(__float2half_rn(acc_o[j2][2] * inv1),
                                    __float2half_rn(acc_o[j2][3] * inv1));
        *reinterpret_cast<__half2*>(g_a + (size_t)r0 * DIM + col)       = v0;
        *reinterpret_cast<__half2*>(g_a + (size_t)(r0 + 8) * DIM + col) = v1;
    }
}

// ---------------------------------------------------------------------------
// Launcher
// ---------------------------------------------------------------------------
extern "C" void kernel_launch(void* const* d_in, const int* in_sizes, int n_in,
                              void* d_out, int out_size)
{
    const float* x     = (const float*)d_in[0];   // [1,4096,1024]
    const float* w_qkv = (const float*)d_in[1];   // [1024,3072]
    const float* w_out = (const float*)d_in[2];   // [1024,1024]
    float* out = (float*)d_out;                   // [1,4096,1024]

    // Pre-pass: round x to fp16; transpose+round both weights (one launch)
    conv_x_kernel<<<SEQ * DIM / 4 / 256, 256>>>(x);
    tconv_kernel<<<dim3((NQKV + DIM) / 32, DIM / 32), dim3(32, 8)>>>(w_qkv, w_out);

    // 1) QKV projection (HMMA fp16, scatter split-fp16 Q/K + fp16 V)
    cudaFuncSetAttribute(gemm_mma_kernel, cudaFuncAttributeMaxDynamicSharedMemorySize, GEMM_SMEM);
    gemm_mma_kernel<<<dim3(NQKV / 128, SEQ / 128), 128, GEMM_SMEM>>>(nullptr, 0);

    // 2) Sparse attention (HMMA, pure cp.async tile loads)
    cudaFuncSetAttribute(attn_kernel, cudaFuncAttributeMaxDynamicSharedMemorySize, ATTN_SMEM);
    attn_kernel<<<dim3(SEQ / 64, NH), 128, ATTN_SMEM>>>();

    // 3) Output projection (HMMA fp16)
    gemm_mma_kernel<<<dim3(DIM / 128, SEQ / 128), 128, GEMM_SMEM>>>(out, 1);
}